// round 2
// baseline (speedup 1.0000x reference)
#include <cuda_runtime.h>
#include <cuda_bf16.h>
#include <math.h>

#define NTOK 294      // 6*7*7 tokens per window
#define NWIN 256      // 16*16 windows
#define NHEAD 8
#define DH 32
#define DIM 256
#define QSCALE 0.17677669529663687f  // 32^-0.5

// -------- scratch (device globals; no allocations allowed) --------
__device__ float g_Q[(size_t)NWIN*NHEAD*NTOK*DH];
__device__ float g_K[(size_t)NWIN*NHEAD*NTOK*DH];
__device__ float g_V[(size_t)NWIN*NHEAD*NTOK*DH];
__device__ float g_O[(size_t)NWIN*NHEAD*NTOK*DH];
__device__ float g_bias[(size_t)NHEAD*NTOK*NTOK];

// ======================================================================
// 1) Precompute relative position bias matrix bias[h][i][j]
//    idx = (ai-aj+5)*169 + (yi-yj+6)*13 + (xi-xj+6)
// ======================================================================
__global__ void bias_kernel(const float* __restrict__ table) {
    int i = blockIdx.x;
    int j = threadIdx.x;
    int ai = i / 49, ri = i % 49, yi = ri / 7, xi = ri % 7;
    int aj = j / 49, rj = j % 49, yj = rj / 7, xj = rj % 7;
    int idx = (ai - aj + 5) * 169 + (yi - yj + 6) * 13 + (xi - xj + 6);
#pragma unroll
    for (int h = 0; h < NHEAD; h++)
        g_bias[((size_t)h * NTOK + i) * NTOK + j] = table[idx * NHEAD + h];
}

// ======================================================================
// 2) QKV projection: C[75264, 768] = Xw[75264, 256] * Wqkv^T
//    Xw row m -> (window Bw = m/294, token t = m%294)
//    x addr: ((l*256 + Bw)*49 + r)*256 + d   where l=t/49, r=t%49
//    Output scattered into g_Q/g_K/g_V [(Bw*8+head)*294 + t]*32 + dh
// ======================================================================
__global__ __launch_bounds__(256) void qkv_gemm(
    const float* __restrict__ x, const float* __restrict__ w) {
    __shared__ float As[16][132];
    __shared__ float Bs[16][132];
    int tid = threadIdx.x;
    int bm = blockIdx.x, bn = blockIdx.y;

    int lrow = tid >> 2;            // 0..63
    int kq   = (tid & 3) << 2;      // 0,4,8,12

    // A global row pointers (two rows per thread)
    const float *ap0, *ap1;
    {
        int m0 = bm * 128 + lrow;
        int Bw = m0 / 294, t = m0 % 294, l = t / 49, r = t % 49;
        ap0 = x + ((size_t)((l * 256 + Bw) * 49 + r)) * 256;
        int m1 = m0 + 64;
        Bw = m1 / 294; t = m1 % 294; l = t / 49; r = t % 49;
        ap1 = x + ((size_t)((l * 256 + Bw) * 49 + r)) * 256;
    }
    const float* bp0 = w + (size_t)(bn * 128 + lrow) * 256;
    const float* bp1 = bp0 + (size_t)64 * 256;

    int tx = tid & 15, ty = tid >> 4;
    float c[8][8];
#pragma unroll
    for (int i = 0; i < 8; i++)
#pragma unroll
        for (int j = 0; j < 8; j++) c[i][j] = 0.f;

    for (int k0 = 0; k0 < 256; k0 += 16) {
        float4 a0 = *(const float4*)(ap0 + k0 + kq);
        float4 a1 = *(const float4*)(ap1 + k0 + kq);
        float4 b0 = *(const float4*)(bp0 + k0 + kq);
        float4 b1 = *(const float4*)(bp1 + k0 + kq);
        __syncthreads();
        As[kq + 0][lrow] = a0.x; As[kq + 1][lrow] = a0.y;
        As[kq + 2][lrow] = a0.z; As[kq + 3][lrow] = a0.w;
        As[kq + 0][lrow + 64] = a1.x; As[kq + 1][lrow + 64] = a1.y;
        As[kq + 2][lrow + 64] = a1.z; As[kq + 3][lrow + 64] = a1.w;
        Bs[kq + 0][lrow] = b0.x; Bs[kq + 1][lrow] = b0.y;
        Bs[kq + 2][lrow] = b0.z; Bs[kq + 3][lrow] = b0.w;
        Bs[kq + 0][lrow + 64] = b1.x; Bs[kq + 1][lrow + 64] = b1.y;
        Bs[kq + 2][lrow + 64] = b1.z; Bs[kq + 3][lrow + 64] = b1.w;
        __syncthreads();
#pragma unroll
        for (int kk = 0; kk < 16; kk++) {
            float av[8], bv[8];
#pragma unroll
            for (int i = 0; i < 8; i++) av[i] = As[kk][ty * 8 + i];
#pragma unroll
            for (int j = 0; j < 8; j++) bv[j] = Bs[kk][tx * 8 + j];
#pragma unroll
            for (int i = 0; i < 8; i++)
#pragma unroll
                for (int j = 0; j < 8; j++) c[i][j] += av[i] * bv[j];
        }
    }

#pragma unroll
    for (int ii = 0; ii < 8; ii++) {
        int m = bm * 128 + ty * 8 + ii;
        int Bw = m / 294, t = m % 294;
#pragma unroll
        for (int jj = 0; jj < 8; jj++) {
            int n = bn * 128 + tx * 8 + jj;
            int part = n >> 8;
            int rem = n & 255;
            int head = rem >> 5, dh = rem & 31;
            size_t o = (((size_t)Bw * 8 + head) * NTOK + t) * DH + dh;
            float v = c[ii][jj];
            if (part == 0)      g_Q[o] = v * QSCALE;
            else if (part == 1) g_K[o] = v;
            else                g_V[o] = v;
        }
    }
}

// ======================================================================
// 3) Attention: one block per (window,head). K,V in smem; one warp per
//    query row (strided). Scores via per-lane j-strips, padded K stride
//    33 to avoid bank conflicts; epilogue via lane=d over V.
// ======================================================================
__global__ __launch_bounds__(256) void attn_kernel() {
    int bh = blockIdx.x;            // Bw*8 + h
    int h = bh & 7;
    extern __shared__ float sm[];
    float* Ks = sm;                 // 294*33
    float* Vs = Ks + NTOK * 33;     // 294*32
    float* P  = Vs + NTOK * 32;     // 8*294
    float* Qr = P + 8 * NTOK;       // 8*32

    const float* Kg = g_K + (size_t)bh * NTOK * DH;
    const float* Vg = g_V + (size_t)bh * NTOK * DH;
    const float* Qg = g_Q + (size_t)bh * NTOK * DH;
    const float* Bb = g_bias + (size_t)h * NTOK * NTOK;

    int tid = threadIdx.x;
    for (int idx = tid; idx < NTOK * DH; idx += 256) {
        int j = idx >> 5, d = idx & 31;
        Ks[j * 33 + d] = Kg[idx];
        Vs[idx] = Vg[idx];
    }
    __syncthreads();

    int w = tid >> 5, lane = tid & 31;
    float* Pw = P + w * NTOK;
    float* Qw = Qr + w * DH;

    for (int i = w; i < NTOK; i += 8) {
        Qw[lane] = Qg[i * DH + lane];
        __syncwarp();

        float s[10];
        const float* kp[10];
#pragma unroll
        for (int jj = 0; jj < 10; jj++) {
            s[jj] = 0.f;
            int j = lane + jj * 32;
            kp[jj] = Ks + (j < NTOK ? j : NTOK - 1) * 33;
        }
#pragma unroll
        for (int d = 0; d < DH; d++) {
            float qd = Qw[d];
#pragma unroll
            for (int jj = 0; jj < 10; jj++)
                s[jj] += qd * kp[jj][d];
        }

        float mx = -1e30f;
        const float* bi = Bb + (size_t)i * NTOK;
#pragma unroll
        for (int jj = 0; jj < 10; jj++) {
            int j = lane + jj * 32;
            if (j < NTOK) {
                s[jj] += bi[j];
                mx = fmaxf(mx, s[jj]);
            } else s[jj] = -1e30f;
        }
#pragma unroll
        for (int o = 16; o > 0; o >>= 1)
            mx = fmaxf(mx, __shfl_xor_sync(0xffffffffu, mx, o));

        float sum = 0.f;
#pragma unroll
        for (int jj = 0; jj < 10; jj++) {
            float e = __expf(s[jj] - mx);
            int j = lane + jj * 32;
            if (j < NTOK) { Pw[j] = e; sum += e; }
        }
#pragma unroll
        for (int o = 16; o > 0; o >>= 1)
            sum += __shfl_xor_sync(0xffffffffu, sum, o);
        float inv = 1.f / sum;
        __syncwarp();

        float acc = 0.f;
#pragma unroll 6
        for (int j = 0; j < NTOK; j++)
            acc += Pw[j] * Vs[j * DH + lane];
        g_O[((size_t)bh * NTOK + i) * DH + lane] = acc * inv;
        __syncwarp();
    }
}

// ======================================================================
// 4) Output projection: out[m][n] = sum_k O_attn[m][k] * w_out[n][k]
//    A gather from g_O [(Bw*8 + k/32)*294 + t]*32 + k%32
//    C scatter to x-like layout ((l*256+Bw)*49 + r)*256 + n
// ======================================================================
__global__ __launch_bounds__(256) void out_gemm(
    const float* __restrict__ w, float* __restrict__ out) {
    __shared__ float As[16][132];
    __shared__ float Bs[16][132];
    int tid = threadIdx.x;
    int bm = blockIdx.x, bn = blockIdx.y;

    int lrow = tid >> 2;
    int kq   = (tid & 3) << 2;

    int m0 = bm * 128 + lrow;
    int Bw0 = m0 / 294, t0 = m0 % 294;
    int m1 = m0 + 64;
    int Bw1 = m1 / 294, t1 = m1 % 294;

    const float* bp0 = w + (size_t)(bn * 128 + lrow) * 256;
    const float* bp1 = bp0 + (size_t)64 * 256;

    int tx = tid & 15, ty = tid >> 4;
    float c[8][8];
#pragma unroll
    for (int i = 0; i < 8; i++)
#pragma unroll
        for (int j = 0; j < 8; j++) c[i][j] = 0.f;

    for (int k0 = 0; k0 < 256; k0 += 16) {
        int kk0 = k0 + kq;
        int head = kk0 >> 5, dh = kk0 & 31;
        const float* ap0 = g_O + (((size_t)Bw0 * 8 + head) * NTOK + t0) * DH + dh;
        const float* ap1 = g_O + (((size_t)Bw1 * 8 + head) * NTOK + t1) * DH + dh;
        float4 a0 = *(const float4*)ap0;
        float4 a1 = *(const float4*)ap1;
        float4 b0 = *(const float4*)(bp0 + k0 + kq);
        float4 b1 = *(const float4*)(bp1 + k0 + kq);
        __syncthreads();
        As[kq + 0][lrow] = a0.x; As[kq + 1][lrow] = a0.y;
        As[kq + 2][lrow] = a0.z; As[kq + 3][lrow] = a0.w;
        As[kq + 0][lrow + 64] = a1.x; As[kq + 1][lrow + 64] = a1.y;
        As[kq + 2][lrow + 64] = a1.z; As[kq + 3][lrow + 64] = a1.w;
        Bs[kq + 0][lrow] = b0.x; Bs[kq + 1][lrow] = b0.y;
        Bs[kq + 2][lrow] = b0.z; Bs[kq + 3][lrow] = b0.w;
        Bs[kq + 0][lrow + 64] = b1.x; Bs[kq + 1][lrow + 64] = b1.y;
        Bs[kq + 2][lrow + 64] = b1.z; Bs[kq + 3][lrow + 64] = b1.w;
        __syncthreads();
#pragma unroll
        for (int kk = 0; kk < 16; kk++) {
            float av[8], bv[8];
#pragma unroll
            for (int i = 0; i < 8; i++) av[i] = As[kk][ty * 8 + i];
#pragma unroll
            for (int j = 0; j < 8; j++) bv[j] = Bs[kk][tx * 8 + j];
#pragma unroll
            for (int i = 0; i < 8; i++)
#pragma unroll
                for (int j = 0; j < 8; j++) c[i][j] += av[i] * bv[j];
        }
    }

#pragma unroll
    for (int ii = 0; ii < 8; ii++) {
        int m = bm * 128 + ty * 8 + ii;
        int Bw = m / 294, t = m % 294, l = t / 49, r = t % 49;
        float* op = out + ((size_t)((l * 256 + Bw) * 49 + r)) * 256 + bn * 128 + tx * 8;
        float4 v0 = make_float4(c[ii][0], c[ii][1], c[ii][2], c[ii][3]);
        float4 v1 = make_float4(c[ii][4], c[ii][5], c[ii][6], c[ii][7]);
        *(float4*)(op)     = v0;
        *(float4*)(op + 4) = v1;
    }
}

// ======================================================================
extern "C" void kernel_launch(void* const* d_in, const int* in_sizes, int n_in,
                              void* d_out, int out_size) {
    const float* x          = (const float*)d_in[0];
    const float* w_qkv      = (const float*)d_in[1];
    const float* w_out      = (const float*)d_in[2];
    const float* bias_table = (const float*)d_in[3];
    float* out = (float*)d_out;

    bias_kernel<<<NTOK, NTOK>>>(bias_table);
    qkv_gemm<<<dim3(588, 6), 256>>>(x, w_qkv);

    int smem = (NTOK * 33 + NTOK * 32 + 8 * NTOK + 8 * DH) * (int)sizeof(float);
    cudaFuncSetAttribute(attn_kernel, cudaFuncAttributeMaxDynamicSharedMemorySize, smem);
    attn_kernel<<<NWIN * NHEAD, 256, smem>>>();

    out_gemm<<<dim3(588, 2), 256>>>(w_out, out);
}

// round 3
// speedup vs baseline: 1.1740x; 1.1740x over previous
#include <cuda_runtime.h>
#include <cuda_bf16.h>
#include <math.h>

#define NTOK 294      // 6*7*7 tokens per window
#define NWIN 256      // 16*16 windows
#define NHEAD 8
#define DH 32
#define DIM 256
#define QSCALE 0.17677669529663687f  // 32^-0.5

// -------- scratch (device globals; no allocations allowed) --------
__device__ float g_Q[(size_t)NWIN*NHEAD*NTOK*DH];
__device__ float g_K[(size_t)NWIN*NHEAD*NTOK*DH];
__device__ float g_V[(size_t)NWIN*NHEAD*NTOK*DH];
__device__ float g_O[(size_t)NWIN*NHEAD*NTOK*DH];
__device__ float g_bias[(size_t)NHEAD*NTOK*NTOK];

// ======================================================================
// 1) Precompute relative position bias matrix bias[h][i][j]
// ======================================================================
__global__ void bias_kernel(const float* __restrict__ table) {
    int i = blockIdx.x;
    int j = threadIdx.x;
    int ai = i / 49, ri = i % 49, yi = ri / 7, xi = ri % 7;
    int aj = j / 49, rj = j % 49, yj = rj / 7, xj = rj % 7;
    int idx = (ai - aj + 5) * 169 + (yi - yj + 6) * 13 + (xi - xj + 6);
#pragma unroll
    for (int h = 0; h < NHEAD; h++)
        g_bias[((size_t)h * NTOK + i) * NTOK + j] = table[idx * NHEAD + h];
}

// ======================================================================
// 2) QKV projection (128x128x16 tiled SGEMM, fused gather/scatter)
// ======================================================================
__global__ __launch_bounds__(256) void qkv_gemm(
    const float* __restrict__ x, const float* __restrict__ w) {
    __shared__ float As[16][132];
    __shared__ float Bs[16][132];
    int tid = threadIdx.x;
    int bm = blockIdx.x, bn = blockIdx.y;

    int lrow = tid >> 2;            // 0..63
    int kq   = (tid & 3) << 2;      // 0,4,8,12

    const float *ap0, *ap1;
    {
        int m0 = bm * 128 + lrow;
        int Bw = m0 / 294, t = m0 % 294, l = t / 49, r = t % 49;
        ap0 = x + ((size_t)((l * 256 + Bw) * 49 + r)) * 256;
        int m1 = m0 + 64;
        Bw = m1 / 294; t = m1 % 294; l = t / 49; r = t % 49;
        ap1 = x + ((size_t)((l * 256 + Bw) * 49 + r)) * 256;
    }
    const float* bp0 = w + (size_t)(bn * 128 + lrow) * 256;
    const float* bp1 = bp0 + (size_t)64 * 256;

    int tx = tid & 15, ty = tid >> 4;
    float c[8][8];
#pragma unroll
    for (int i = 0; i < 8; i++)
#pragma unroll
        for (int j = 0; j < 8; j++) c[i][j] = 0.f;

    for (int k0 = 0; k0 < 256; k0 += 16) {
        float4 a0 = *(const float4*)(ap0 + k0 + kq);
        float4 a1 = *(const float4*)(ap1 + k0 + kq);
        float4 b0 = *(const float4*)(bp0 + k0 + kq);
        float4 b1 = *(const float4*)(bp1 + k0 + kq);
        __syncthreads();
        As[kq + 0][lrow] = a0.x; As[kq + 1][lrow] = a0.y;
        As[kq + 2][lrow] = a0.z; As[kq + 3][lrow] = a0.w;
        As[kq + 0][lrow + 64] = a1.x; As[kq + 1][lrow + 64] = a1.y;
        As[kq + 2][lrow + 64] = a1.z; As[kq + 3][lrow + 64] = a1.w;
        Bs[kq + 0][lrow] = b0.x; Bs[kq + 1][lrow] = b0.y;
        Bs[kq + 2][lrow] = b0.z; Bs[kq + 3][lrow] = b0.w;
        Bs[kq + 0][lrow + 64] = b1.x; Bs[kq + 1][lrow + 64] = b1.y;
        Bs[kq + 2][lrow + 64] = b1.z; Bs[kq + 3][lrow + 64] = b1.w;
        __syncthreads();
#pragma unroll
        for (int kk = 0; kk < 16; kk++) {
            float av[8], bv[8];
#pragma unroll
            for (int i = 0; i < 8; i++) av[i] = As[kk][ty * 8 + i];
#pragma unroll
            for (int j = 0; j < 8; j++) bv[j] = Bs[kk][tx * 8 + j];
#pragma unroll
            for (int i = 0; i < 8; i++)
#pragma unroll
                for (int j = 0; j < 8; j++) c[i][j] += av[i] * bv[j];
        }
    }

#pragma unroll
    for (int ii = 0; ii < 8; ii++) {
        int m = bm * 128 + ty * 8 + ii;
        int Bw = m / 294, t = m % 294;
#pragma unroll
        for (int jj = 0; jj < 8; jj++) {
            int n = bn * 128 + tx * 8 + jj;
            int part = n >> 8;
            int rem = n & 255;
            int head = rem >> 5, dh = rem & 31;
            size_t o = (((size_t)Bw * 8 + head) * NTOK + t) * DH + dh;
            float v = c[ii][jj];
            if (part == 0)      g_Q[o] = v * QSCALE;
            else if (part == 1) g_K[o] = v;
            else                g_V[o] = v;
        }
    }
}

// ======================================================================
// 3) Attention: one block per (window,head). 4 query rows per warp,
//    float4 smem reads, bias preloaded into accumulators.
//    Ks padded stride 36 (conflict-free LDS.128); Vs/P padded to 296 rows.
// ======================================================================
#define KSTR 36
#define JPAD 296
__global__ __launch_bounds__(256) void attn_kernel() {
    int bh = blockIdx.x;            // Bw*8 + h
    int h = bh & 7;
    extern __shared__ float sm[];
    float* Ks = sm;                       // 294*36
    float* Vs = Ks + NTOK * KSTR;         // 296*32
    float* P  = Vs + JPAD * DH;           // 8*4*296
    float* Qr = P + 8 * 4 * JPAD;         // 8*4*32

    const float* Kg = g_K + (size_t)bh * NTOK * DH;
    const float* Vg = g_V + (size_t)bh * NTOK * DH;
    const float* Qg = g_Q + (size_t)bh * NTOK * DH;
    const float* Bb = g_bias + (size_t)h * NTOK * NTOK;

    int tid = threadIdx.x;
    for (int idx = tid; idx < NTOK * DH; idx += 256) {
        int j = idx >> 5, d = idx & 31;
        Ks[j * KSTR + d] = Kg[idx];
    }
    for (int idx = tid; idx < JPAD * DH; idx += 256) {
        int j = idx >> 5;
        Vs[idx] = (j < NTOK) ? Vg[idx] : 0.f;
    }
    __syncthreads();

    int w = tid >> 5, lane = tid & 31;
    float* Pw = P + w * 4 * JPAD;
    float* Qw = Qr + w * 4 * DH;

    // zero the padded tail of P once (rows j=294,295 never written in-loop)
    if (lane < 2) {
#pragma unroll
        for (int r = 0; r < 4; r++) Pw[r * JPAD + NTOK + lane] = 0.f;
    }

    // per-lane K strip pointers (clamped; OOB strips masked via -inf scores)
    const float* kp[10];
#pragma unroll
    for (int jj = 0; jj < 10; jj++) {
        int j = lane + jj * 32;
        kp[jj] = Ks + (j < NTOK ? j : NTOK - 1) * KSTR;
    }

    for (int i0 = w * 4; i0 < NTOK; i0 += 32) {
        // stage 4 q rows into smem
#pragma unroll
        for (int r = 0; r < 4; r++) {
            int i = i0 + r; if (i >= NTOK) i = NTOK - 1;
            Qw[r * DH + lane] = Qg[i * DH + lane];
        }
        __syncwarp();

        // accumulators initialized with bias (hides LDG latency under QK)
        float s[4][10];
#pragma unroll
        for (int r = 0; r < 4; r++) {
            int i = i0 + r; if (i >= NTOK) i = NTOK - 1;
            const float* bi = Bb + (size_t)i * NTOK;
#pragma unroll
            for (int jj = 0; jj < 10; jj++) {
                int j = lane + jj * 32;
                s[r][jj] = (j < NTOK) ? bi[j] : -1e30f;
            }
        }

        // QK^T: per d4-step, 14 LDS.128 feed 160 FMA
#pragma unroll
        for (int d4 = 0; d4 < 8; d4++) {
            float4 q0 = *(const float4*)(Qw + 0 * DH + d4 * 4);
            float4 q1 = *(const float4*)(Qw + 1 * DH + d4 * 4);
            float4 q2 = *(const float4*)(Qw + 2 * DH + d4 * 4);
            float4 q3 = *(const float4*)(Qw + 3 * DH + d4 * 4);
#pragma unroll
            for (int jj = 0; jj < 10; jj++) {
                float4 kv = *(const float4*)(kp[jj] + d4 * 4);
                s[0][jj] += q0.x*kv.x + q0.y*kv.y + q0.z*kv.z + q0.w*kv.w;
                s[1][jj] += q1.x*kv.x + q1.y*kv.y + q1.z*kv.z + q1.w*kv.w;
                s[2][jj] += q2.x*kv.x + q2.y*kv.y + q2.z*kv.z + q2.w*kv.w;
                s[3][jj] += q3.x*kv.x + q3.y*kv.y + q3.z*kv.z + q3.w*kv.w;
            }
        }

        // softmax per row
        float inv[4];
#pragma unroll
        for (int r = 0; r < 4; r++) {
            float mx = -1e30f;
#pragma unroll
            for (int jj = 0; jj < 10; jj++) mx = fmaxf(mx, s[r][jj]);
#pragma unroll
            for (int o = 16; o > 0; o >>= 1)
                mx = fmaxf(mx, __shfl_xor_sync(0xffffffffu, mx, o));
            float sum = 0.f;
#pragma unroll
            for (int jj = 0; jj < 10; jj++) {
                float e = __expf(s[r][jj] - mx);
                int j = lane + jj * 32;
                if (j < NTOK) { Pw[r * JPAD + j] = e; sum += e; }
            }
#pragma unroll
            for (int o = 16; o > 0; o >>= 1)
                sum += __shfl_xor_sync(0xffffffffu, sum, o);
            inv[r] = 1.f / sum;
        }
        __syncwarp();

        // A*V: 4 rows share each V load; P via float4 broadcast
        float acc0 = 0.f, acc1 = 0.f, acc2 = 0.f, acc3 = 0.f;
#pragma unroll 2
        for (int jb = 0; jb < JPAD / 4; jb++) {
            const float* vb = Vs + jb * 4 * DH + lane;
            float v0 = vb[0], v1 = vb[DH], v2 = vb[2 * DH], v3 = vb[3 * DH];
            float4 p0 = *(const float4*)(Pw + 0 * JPAD + jb * 4);
            float4 p1 = *(const float4*)(Pw + 1 * JPAD + jb * 4);
            float4 p2 = *(const float4*)(Pw + 2 * JPAD + jb * 4);
            float4 p3 = *(const float4*)(Pw + 3 * JPAD + jb * 4);
            acc0 += p0.x*v0 + p0.y*v1 + p0.z*v2 + p0.w*v3;
            acc1 += p1.x*v0 + p1.y*v1 + p1.z*v2 + p1.w*v3;
            acc2 += p2.x*v0 + p2.y*v1 + p2.z*v2 + p2.w*v3;
            acc3 += p3.x*v0 + p3.y*v1 + p3.z*v2 + p3.w*v3;
        }

        float accs[4] = {acc0, acc1, acc2, acc3};
#pragma unroll
        for (int r = 0; r < 4; r++) {
            int i = i0 + r;
            if (i < NTOK)
                g_O[((size_t)bh * NTOK + i) * DH + lane] = accs[r] * inv[r];
        }
        __syncwarp();
    }
}

// ======================================================================
// 4) Output projection (tiled SGEMM, fused gather from g_O + scatter)
// ======================================================================
__global__ __launch_bounds__(256) void out_gemm(
    const float* __restrict__ w, float* __restrict__ out) {
    __shared__ float As[16][132];
    __shared__ float Bs[16][132];
    int tid = threadIdx.x;
    int bm = blockIdx.x, bn = blockIdx.y;

    int lrow = tid >> 2;
    int kq   = (tid & 3) << 2;

    int m0 = bm * 128 + lrow;
    int Bw0 = m0 / 294, t0 = m0 % 294;
    int m1 = m0 + 64;
    int Bw1 = m1 / 294, t1 = m1 % 294;

    const float* bp0 = w + (size_t)(bn * 128 + lrow) * 256;
    const float* bp1 = bp0 + (size_t)64 * 256;

    int tx = tid & 15, ty = tid >> 4;
    float c[8][8];
#pragma unroll
    for (int i = 0; i < 8; i++)
#pragma unroll
        for (int j = 0; j < 8; j++) c[i][j] = 0.f;

    for (int k0 = 0; k0 < 256; k0 += 16) {
        int kk0 = k0 + kq;
        int head = kk0 >> 5, dh = kk0 & 31;
        const float* ap0 = g_O + (((size_t)Bw0 * 8 + head) * NTOK + t0) * DH + dh;
        const float* ap1 = g_O + (((size_t)Bw1 * 8 + head) * NTOK + t1) * DH + dh;
        float4 a0 = *(const float4*)ap0;
        float4 a1 = *(const float4*)ap1;
        float4 b0 = *(const float4*)(bp0 + k0 + kq);
        float4 b1 = *(const float4*)(bp1 + k0 + kq);
        __syncthreads();
        As[kq + 0][lrow] = a0.x; As[kq + 1][lrow] = a0.y;
        As[kq + 2][lrow] = a0.z; As[kq + 3][lrow] = a0.w;
        As[kq + 0][lrow + 64] = a1.x; As[kq + 1][lrow + 64] = a1.y;
        As[kq + 2][lrow + 64] = a1.z; As[kq + 3][lrow + 64] = a1.w;
        Bs[kq + 0][lrow] = b0.x; Bs[kq + 1][lrow] = b0.y;
        Bs[kq + 2][lrow] = b0.z; Bs[kq + 3][lrow] = b0.w;
        Bs[kq + 0][lrow + 64] = b1.x; Bs[kq + 1][lrow + 64] = b1.y;
        Bs[kq + 2][lrow + 64] = b1.z; Bs[kq + 3][lrow + 64] = b1.w;
        __syncthreads();
#pragma unroll
        for (int kk = 0; kk < 16; kk++) {
            float av[8], bv[8];
#pragma unroll
            for (int i = 0; i < 8; i++) av[i] = As[kk][ty * 8 + i];
#pragma unroll
            for (int j = 0; j < 8; j++) bv[j] = Bs[kk][tx * 8 + j];
#pragma unroll
            for (int i = 0; i < 8; i++)
#pragma unroll
                for (int j = 0; j < 8; j++) c[i][j] += av[i] * bv[j];
        }
    }

#pragma unroll
    for (int ii = 0; ii < 8; ii++) {
        int m = bm * 128 + ty * 8 + ii;
        int Bw = m / 294, t = m % 294, l = t / 49, r = t % 49;
        float* op = out + ((size_t)((l * 256 + Bw) * 49 + r)) * 256 + bn * 128 + tx * 8;
        float4 v0 = make_float4(c[ii][0], c[ii][1], c[ii][2], c[ii][3]);
        float4 v1 = make_float4(c[ii][4], c[ii][5], c[ii][6], c[ii][7]);
        *(float4*)(op)     = v0;
        *(float4*)(op + 4) = v1;
    }
}

// ======================================================================
extern "C" void kernel_launch(void* const* d_in, const int* in_sizes, int n_in,
                              void* d_out, int out_size) {
    const float* x          = (const float*)d_in[0];
    const float* w_qkv      = (const float*)d_in[1];
    const float* w_out      = (const float*)d_in[2];
    const float* bias_table = (const float*)d_in[3];
    float* out = (float*)d_out;

    bias_kernel<<<NTOK, NTOK>>>(bias_table);
    qkv_gemm<<<dim3(588, 6), 256>>>(x, w_qkv);

    int smem = (NTOK * KSTR + JPAD * DH + 8 * 4 * JPAD + 8 * 4 * DH) * (int)sizeof(float);
    cudaFuncSetAttribute(attn_kernel, cudaFuncAttributeMaxDynamicSharedMemorySize, smem);
    attn_kernel<<<NWIN * NHEAD, 256, smem>>>();

    out_gemm<<<dim3(588, 2), 256>>>(w_out, out);
}

// round 4
// speedup vs baseline: 1.3680x; 1.1652x over previous
#include <cuda_runtime.h>
#include <cuda_bf16.h>
#include <math.h>

#define NTOK 294      // 6*7*7 tokens per window
#define NWIN 256      // 16*16 windows
#define NHEAD 8
#define DH 32
#define DIM 256
#define QSCALE 0.17677669529663687f  // 32^-0.5

// -------- scratch (device globals; no allocations allowed) --------
__device__ float g_Q[(size_t)NWIN*NHEAD*NTOK*DH];
__device__ float g_K[(size_t)NWIN*NHEAD*NTOK*DH];
__device__ float g_V[(size_t)NWIN*NHEAD*NTOK*DH];
__device__ float g_O[(size_t)NWIN*NHEAD*NTOK*DH];
__device__ float g_bias[(size_t)NHEAD*NTOK*NTOK];

// ======================================================================
// 1) Precompute relative position bias matrix bias[h][i][j]
// ======================================================================
__global__ void bias_kernel(const float* __restrict__ table) {
    int i = blockIdx.x;
    int j = threadIdx.x;
    int ai = i / 49, ri = i % 49, yi = ri / 7, xi = ri % 7;
    int aj = j / 49, rj = j % 49, yj = rj / 7, xj = rj % 7;
    int idx = (ai - aj + 5) * 169 + (yi - yj + 6) * 13 + (xi - xj + 6);
#pragma unroll
    for (int h = 0; h < NHEAD; h++)
        g_bias[((size_t)h * NTOK + i) * NTOK + j] = table[idx * NHEAD + h];
}

// ======================================================================
// 2) QKV projection (128x128x16 tiled SGEMM, fused gather/scatter)
// ======================================================================
__global__ __launch_bounds__(256) void qkv_gemm(
    const float* __restrict__ x, const float* __restrict__ w) {
    __shared__ float As[16][132];
    __shared__ float Bs[16][132];
    int tid = threadIdx.x;
    int bm = blockIdx.x, bn = blockIdx.y;

    int lrow = tid >> 2;            // 0..63
    int kq   = (tid & 3) << 2;      // 0,4,8,12

    const float *ap0, *ap1;
    {
        int m0 = bm * 128 + lrow;
        int Bw = m0 / 294, t = m0 % 294, l = t / 49, r = t % 49;
        ap0 = x + ((size_t)((l * 256 + Bw) * 49 + r)) * 256;
        int m1 = m0 + 64;
        Bw = m1 / 294; t = m1 % 294; l = t / 49; r = t % 49;
        ap1 = x + ((size_t)((l * 256 + Bw) * 49 + r)) * 256;
    }
    const float* bp0 = w + (size_t)(bn * 128 + lrow) * 256;
    const float* bp1 = bp0 + (size_t)64 * 256;

    int tx = tid & 15, ty = tid >> 4;
    float c[8][8];
#pragma unroll
    for (int i = 0; i < 8; i++)
#pragma unroll
        for (int j = 0; j < 8; j++) c[i][j] = 0.f;

    for (int k0 = 0; k0 < 256; k0 += 16) {
        float4 a0 = *(const float4*)(ap0 + k0 + kq);
        float4 a1 = *(const float4*)(ap1 + k0 + kq);
        float4 b0 = *(const float4*)(bp0 + k0 + kq);
        float4 b1 = *(const float4*)(bp1 + k0 + kq);
        __syncthreads();
        As[kq + 0][lrow] = a0.x; As[kq + 1][lrow] = a0.y;
        As[kq + 2][lrow] = a0.z; As[kq + 3][lrow] = a0.w;
        As[kq + 0][lrow + 64] = a1.x; As[kq + 1][lrow + 64] = a1.y;
        As[kq + 2][lrow + 64] = a1.z; As[kq + 3][lrow + 64] = a1.w;
        Bs[kq + 0][lrow] = b0.x; Bs[kq + 1][lrow] = b0.y;
        Bs[kq + 2][lrow] = b0.z; Bs[kq + 3][lrow] = b0.w;
        Bs[kq + 0][lrow + 64] = b1.x; Bs[kq + 1][lrow + 64] = b1.y;
        Bs[kq + 2][lrow + 64] = b1.z; Bs[kq + 3][lrow + 64] = b1.w;
        __syncthreads();
#pragma unroll
        for (int kk = 0; kk < 16; kk++) {
            float av[8], bv[8];
#pragma unroll
            for (int i = 0; i < 8; i++) av[i] = As[kk][ty * 8 + i];
#pragma unroll
            for (int j = 0; j < 8; j++) bv[j] = Bs[kk][tx * 8 + j];
#pragma unroll
            for (int i = 0; i < 8; i++)
#pragma unroll
                for (int j = 0; j < 8; j++) c[i][j] += av[i] * bv[j];
        }
    }

#pragma unroll
    for (int ii = 0; ii < 8; ii++) {
        int m = bm * 128 + ty * 8 + ii;
        int Bw = m / 294, t = m % 294;
#pragma unroll
        for (int jj = 0; jj < 8; jj++) {
            int n = bn * 128 + tx * 8 + jj;
            int part = n >> 8;
            int rem = n & 255;
            int head = rem >> 5, dh = rem & 31;
            size_t o = (((size_t)Bw * 8 + head) * NTOK + t) * DH + dh;
            float v = c[ii][jj];
            if (part == 0)      g_Q[o] = v * QSCALE;
            else if (part == 1) g_K[o] = v;
            else                g_V[o] = v;
        }
    }
}

// ======================================================================
// 3) Attention: one block per (window,head). 4 query rows per warp.
//    Strip-wise AV with tiny double-buffered per-warp P patch so smem
//    fits 2 blocks/SM (occupancy doubles vs R3).
// ======================================================================
#define KSTR 36
#define VROWS 320   // 294 rounded to 10 strips of 32, zero padded
__global__ __launch_bounds__(256, 2) void attn_kernel() {
    int bh = blockIdx.x;            // Bw*8 + h
    int h = bh & 7;
    extern __shared__ float sm[];
    float* Ks = sm;                       // 294*36      = 10584
    float* Vs = Ks + NTOK * KSTR;         // 320*32      = 10240
    float* Ps = Vs + VROWS * DH;          // 8 warps*256 =  2048 (dbl-buf 4x32)
    float* Qr = Ps + 8 * 256;             // 8 warps*128 =  1024
    // total 23896 floats = 93.3 KB -> 2 blocks/SM

    const float* Kg = g_K + (size_t)bh * NTOK * DH;
    const float* Vg = g_V + (size_t)bh * NTOK * DH;
    const float* Qg = g_Q + (size_t)bh * NTOK * DH;
    const float* Bb = g_bias + (size_t)h * NTOK * NTOK;

    int tid = threadIdx.x;
    for (int idx = tid; idx < NTOK * DH; idx += 256) {
        int j = idx >> 5, d = idx & 31;
        Ks[j * KSTR + d] = Kg[idx];
    }
    for (int idx = tid; idx < VROWS * DH; idx += 256) {
        int j = idx >> 5;
        Vs[idx] = (j < NTOK) ? Vg[idx] : 0.f;
    }
    __syncthreads();

    int w = tid >> 5, lane = tid & 31;
    float* Pw = Ps + w * 256;             // two 128-float buffers
    float* Qw = Qr + w * 4 * DH;

    // per-lane K strip pointers (clamped; OOB strips give e=0 via -1e30 bias)
    const float* kp[10];
#pragma unroll
    for (int jj = 0; jj < 10; jj++) {
        int j = lane + jj * 32;
        kp[jj] = Ks + (j < NTOK ? j : NTOK - 1) * KSTR;
    }

    for (int i0 = w * 4; i0 < NTOK; i0 += 32) {
        // stage 4 q rows into smem
#pragma unroll
        for (int r = 0; r < 4; r++) {
            int i = i0 + r; if (i >= NTOK) i = NTOK - 1;
            Qw[r * DH + lane] = Qg[i * DH + lane];
        }
        __syncwarp();

        // accumulators initialized with bias (hides LDG latency under QK)
        float s[4][10];
#pragma unroll
        for (int r = 0; r < 4; r++) {
            int i = i0 + r; if (i >= NTOK) i = NTOK - 1;
            const float* bi = Bb + (size_t)i * NTOK;
#pragma unroll
            for (int jj = 0; jj < 10; jj++) {
                int j = lane + jj * 32;
                s[r][jj] = (j < NTOK) ? bi[j] : -1e30f;
            }
        }

        // QK^T: per d4-step, 14 LDS.128 feed 160 FMA
#pragma unroll
        for (int d4 = 0; d4 < 8; d4++) {
            float4 q0 = *(const float4*)(Qw + 0 * DH + d4 * 4);
            float4 q1 = *(const float4*)(Qw + 1 * DH + d4 * 4);
            float4 q2 = *(const float4*)(Qw + 2 * DH + d4 * 4);
            float4 q3 = *(const float4*)(Qw + 3 * DH + d4 * 4);
#pragma unroll
            for (int jj = 0; jj < 10; jj++) {
                float4 kv = *(const float4*)(kp[jj] + d4 * 4);
                s[0][jj] += q0.x*kv.x + q0.y*kv.y + q0.z*kv.z + q0.w*kv.w;
                s[1][jj] += q1.x*kv.x + q1.y*kv.y + q1.z*kv.z + q1.w*kv.w;
                s[2][jj] += q2.x*kv.x + q2.y*kv.y + q2.z*kv.z + q2.w*kv.w;
                s[3][jj] += q3.x*kv.x + q3.y*kv.y + q3.z*kv.z + q3.w*kv.w;
            }
        }

        // softmax per row (e kept in s[][]; OOB j -> exp(-1e30-mx) = 0)
        float inv[4];
#pragma unroll
        for (int r = 0; r < 4; r++) {
            float mx = -1e30f;
#pragma unroll
            for (int jj = 0; jj < 10; jj++) mx = fmaxf(mx, s[r][jj]);
#pragma unroll
            for (int o = 16; o > 0; o >>= 1)
                mx = fmaxf(mx, __shfl_xor_sync(0xffffffffu, mx, o));
            float sum = 0.f;
#pragma unroll
            for (int jj = 0; jj < 10; jj++) {
                float e = __expf(s[r][jj] - mx);
                s[r][jj] = e;
                sum += e;
            }
#pragma unroll
            for (int o = 16; o > 0; o >>= 1)
                sum += __shfl_xor_sync(0xffffffffu, sum, o);
            inv[r] = 1.f / sum;
        }

        // strip-wise A*V: per strip, park 4x32 e-values in the small
        // double-buffered P patch, then all lanes FMA vs V columns.
        float acc0 = 0.f, acc1 = 0.f, acc2 = 0.f, acc3 = 0.f;
#pragma unroll
        for (int jj = 0; jj < 10; jj++) {
            float* Pb = Pw + (jj & 1) * 128;
            Pb[0 * 32 + lane] = s[0][jj];
            Pb[1 * 32 + lane] = s[1][jj];
            Pb[2 * 32 + lane] = s[2][jj];
            Pb[3 * 32 + lane] = s[3][jj];
            __syncwarp();
            const float* vb = Vs + jj * 32 * DH + lane;
#pragma unroll
            for (int m4 = 0; m4 < 8; m4++) {
                float v0 = vb[(m4 * 4 + 0) * DH];
                float v1 = vb[(m4 * 4 + 1) * DH];
                float v2 = vb[(m4 * 4 + 2) * DH];
                float v3 = vb[(m4 * 4 + 3) * DH];
                float4 p0 = *(const float4*)(Pb + 0 * 32 + m4 * 4);
                float4 p1 = *(const float4*)(Pb + 1 * 32 + m4 * 4);
                float4 p2 = *(const float4*)(Pb + 2 * 32 + m4 * 4);
                float4 p3 = *(const float4*)(Pb + 3 * 32 + m4 * 4);
                acc0 += p0.x*v0 + p0.y*v1 + p0.z*v2 + p0.w*v3;
                acc1 += p1.x*v0 + p1.y*v1 + p1.z*v2 + p1.w*v3;
                acc2 += p2.x*v0 + p2.y*v1 + p2.z*v2 + p2.w*v3;
                acc3 += p3.x*v0 + p3.y*v1 + p3.z*v2 + p3.w*v3;
            }
            __syncwarp();   // protect buffer reuse (parity covers adjacent strip)
        }

        float accs[4] = {acc0, acc1, acc2, acc3};
#pragma unroll
        for (int r = 0; r < 4; r++) {
            int i = i0 + r;
            if (i < NTOK)
                g_O[((size_t)bh * NTOK + i) * DH + lane] = accs[r] * inv[r];
        }
        __syncwarp();
    }
}

// ======================================================================
// 4) Output projection (tiled SGEMM, fused gather from g_O + scatter)
// ======================================================================
__global__ __launch_bounds__(256) void out_gemm(
    const float* __restrict__ w, float* __restrict__ out) {
    __shared__ float As[16][132];
    __shared__ float Bs[16][132];
    int tid = threadIdx.x;
    int bm = blockIdx.x, bn = blockIdx.y;

    int lrow = tid >> 2;
    int kq   = (tid & 3) << 2;

    int m0 = bm * 128 + lrow;
    int Bw0 = m0 / 294, t0 = m0 % 294;
    int m1 = m0 + 64;
    int Bw1 = m1 / 294, t1 = m1 % 294;

    const float* bp0 = w + (size_t)(bn * 128 + lrow) * 256;
    const float* bp1 = bp0 + (size_t)64 * 256;

    int tx = tid & 15, ty = tid >> 4;
    float c[8][8];
#pragma unroll
    for (int i = 0; i < 8; i++)
#pragma unroll
        for (int j = 0; j < 8; j++) c[i][j] = 0.f;

    for (int k0 = 0; k0 < 256; k0 += 16) {
        int kk0 = k0 + kq;
        int head = kk0 >> 5, dh = kk0 & 31;
        const float* ap0 = g_O + (((size_t)Bw0 * 8 + head) * NTOK + t0) * DH + dh;
        const float* ap1 = g_O + (((size_t)Bw1 * 8 + head) * NTOK + t1) * DH + dh;
        float4 a0 = *(const float4*)ap0;
        float4 a1 = *(const float4*)ap1;
        float4 b0 = *(const float4*)(bp0 + k0 + kq);
        float4 b1 = *(const float4*)(bp1 + k0 + kq);
        __syncthreads();
        As[kq + 0][lrow] = a0.x; As[kq + 1][lrow] = a0.y;
        As[kq + 2][lrow] = a0.z; As[kq + 3][lrow] = a0.w;
        As[kq + 0][lrow + 64] = a1.x; As[kq + 1][lrow + 64] = a1.y;
        As[kq + 2][lrow + 64] = a1.z; As[kq + 3][lrow + 64] = a1.w;
        Bs[kq + 0][lrow] = b0.x; Bs[kq + 1][lrow] = b0.y;
        Bs[kq + 2][lrow] = b0.z; Bs[kq + 3][lrow] = b0.w;
        Bs[kq + 0][lrow + 64] = b1.x; Bs[kq + 1][lrow + 64] = b1.y;
        Bs[kq + 2][lrow + 64] = b1.z; Bs[kq + 3][lrow + 64] = b1.w;
        __syncthreads();
#pragma unroll
        for (int kk = 0; kk < 16; kk++) {
            float av[8], bv[8];
#pragma unroll
            for (int i = 0; i < 8; i++) av[i] = As[kk][ty * 8 + i];
#pragma unroll
            for (int j = 0; j < 8; j++) bv[j] = Bs[kk][tx * 8 + j];
#pragma unroll
            for (int i = 0; i < 8; i++)
#pragma unroll
                for (int j = 0; j < 8; j++) c[i][j] += av[i] * bv[j];
        }
    }

#pragma unroll
    for (int ii = 0; ii < 8; ii++) {
        int m = bm * 128 + ty * 8 + ii;
        int Bw = m / 294, t = m % 294, l = t / 49, r = t % 49;
        float* op = out + ((size_t)((l * 256 + Bw) * 49 + r)) * 256 + bn * 128 + tx * 8;
        float4 v0 = make_float4(c[ii][0], c[ii][1], c[ii][2], c[ii][3]);
        float4 v1 = make_float4(c[ii][4], c[ii][5], c[ii][6], c[ii][7]);
        *(float4*)(op)     = v0;
        *(float4*)(op + 4) = v1;
    }
}

// ======================================================================
extern "C" void kernel_launch(void* const* d_in, const int* in_sizes, int n_in,
                              void* d_out, int out_size) {
    const float* x          = (const float*)d_in[0];
    const float* w_qkv      = (const float*)d_in[1];
    const float* w_out      = (const float*)d_in[2];
    const float* bias_table = (const float*)d_in[3];
    float* out = (float*)d_out;

    bias_kernel<<<NTOK, NTOK>>>(bias_table);
    qkv_gemm<<<dim3(588, 6), 256>>>(x, w_qkv);

    int smem = (NTOK * KSTR + VROWS * DH + 8 * 256 + 8 * 128) * (int)sizeof(float);
    cudaFuncSetAttribute(attn_kernel, cudaFuncAttributeMaxDynamicSharedMemorySize, smem);
    attn_kernel<<<NWIN * NHEAD, 256, smem>>>();

    out_gemm<<<dim3(588, 2), 256>>>(w_out, out);
}